// round 16
// baseline (speedup 1.0000x reference)
#include <cuda_runtime.h>
typedef unsigned int u32;

#define HH 4096
#define ROWF 12288          // floats per image row
#define TPB 192             // one thread per (col, chan), 64-col strips
#define RS 216              // floats per staged row (64+8 halo cols)
#define BUFF 864            // floats per 4-row stage buffer
#define BUFB 3456           // bytes per 4-row stage buffer

// horizontal taps: radius-1, renormalized to unit applied mass
#define KH0 0.78698593f
#define KH1 0.10650699f
// vertical taps: radius-2, reference-normalized
#define K0f 0.78657070f
#define K1f 0.10645078f
#define K2f 2.63866e-4f
#define DECAYf 0.60653065971263342f
#define OMDf   0.39346934028736658f
#define INV3f  0.33333322222f        // 1/(3 + 1e-6)

__global__ __launch_bounds__(TPB, 10)
void chem_kernel(const float* __restrict__ D, const float* __restrict__ Cm,
                 float* __restrict__ out)
{
    __shared__ float stage[4 * BUFF];    // 13824 B, 4-deep 4-row ring
    __shared__ float shI[2][4][TPB];     // 6144 B, batch-parity double buffer

    const int tid = threadIdx.x;
    const int c   = tid % 3;
    const int wb_ = tid - c;
    const int w0  = blockIdx.x << 6;     // 64 strips of 64 cols
    const int by  = blockIdx.y;          // 23 row chunks: 179,179,178*21
    const int h0  = 178 * by + (by < 2 ? by : 2);
    const int hend = h0 + (by < 2 ? 179 : 178);

    const float cc0 = __ldg(Cm + 0 + c);
    const float cc1 = __ldg(Cm + 3 + c);
    const float cc2 = __ldg(Cm + 6 + c);

    // cp.async loader: 216 float4 per 4-row batch; m0 covers vec tid (all 192),
    // m1 covers vec 192+tid for tid<24 (row 3, v=30+tid)
    const int  j0   = tid / 54, v0 = tid - 54 * j0;
    const int  g0   = (w0 - 4) * 3 + 4 * v0;
    const bool cok0 = (g0 >= 0) && (g0 + 4 <= ROWF);
    const bool sec  = tid < 24;
    const int  g1   = (w0 - 4) * 3 + 4 * (30 + tid);
    const bool cok1 = sec && (g1 >= 0) && (g1 + 4 <= ROWF);

    const u32 sb  = (u32)__cvta_generic_to_shared(stage);
    const u32 sA0 = sb + (u32)((j0 * RS + 4 * v0) * 4);
    const u32 sA1 = sb + (u32)((3 * RS + 4 * (30 + tid)) * 4);

    float hb[8] = {0,0,0,0,0,0,0,0};   // horizontal-blur ring
    float dr[4] = {0,0,0,0};           // raw density ring (lag 2)
    float sr[4] = {0,0,0,0};           // soft-cloud ring (lag 2)
    float ds[4];                       // density stash (MIX consumes pre-refill)
    float siir = 0.f;

    int rb  = h0 - 22;                 // 51 batches of 4 rows; MIX from k=7
    int rom = h0;                      // MIX row base
    float* opm = out + (long)h0 * ROWF + w0 * 3 + tid;

#define ISSUE(RB, SBUF) { \
    const int  row = (RB) + j0; \
    const int  sz  = (cok0 && row >= 0 && row < HH) ? 16 : 0; \
    const float* gp = sz ? (D + (long)row * ROWF + g0) : D; \
    asm volatile("cp.async.cg.shared.global [%0], [%1], 16, %2;\n" \
                 :: "r"(sA0 + (u32)(SBUF) * BUFB), "l"(gp), "r"(sz) : "memory"); \
    if (sec) { \
        const int  row1 = (RB) + 3; \
        const int  sz1  = (cok1 && row1 >= 0 && row1 < HH) ? 16 : 0; \
        const float* gp1 = sz1 ? (D + (long)row1 * ROWF + g1) : D; \
        asm volatile("cp.async.cg.shared.global [%0], [%1], 16, %2;\n" \
                     :: "r"(sA1 + (u32)(SBUF) * BUFB), "l"(gp1), "r"(sz1) : "memory"); \
    } \
    asm volatile("cp.async.commit_group;\n" ::: "memory"); }

// Row at phase S; output row ro = r-2 (lag-2 rings). shI/ds always written;
// warm batches' values are simply never MIXed.
#define ROWE(S, J, PH) { \
    const float* bp = stgf + (J) * RS; \
    const float xm1 = bp[tid+9], x0 = bp[tid+12], xp1 = bp[tid+15]; \
    siir = fmaf(DECAYf, siir, x0); \
    hb[(S)&7] = fmaf(xm1 + xp1, KH1, x0 * KH0); \
    float vb_ = hb[((S)+6)&7] * K0f; \
    vb_ = fmaf(hb[((S)+5)&7] + hb[((S)+7)&7], K1f, vb_); \
    vb_ = fmaf(hb[((S)+4)&7] + hb[(S)&7],     K2f, vb_); \
    const float d_o = dr[((S)+2)&3]; \
    const float s_o = sr[((S)+2)&3]; \
    ds[J] = d_o; \
    shI[PH][J][tid] = s_o + (d_o * INV3f) * (vb_ - s_o); \
    dr[(S)&3] = x0; \
    sr[(S)&3] = OMDf * siir; }

#define MIX1(PB, J) { \
    if (rom + (J) < hend) { \
        const float i0 = shI[PB][J][wb_], i1 = shI[PB][J][wb_+1], i2 = shI[PB][J][wb_+2]; \
        const float inh = cc0*i0 + cc1*i1 + cc2*i2; \
        const float arg = (ds[J] - inh) * INV3f; \
        float t; asm("tanh.approx.f32 %0, %1;" : "=f"(t) : "f"(arg)); \
        __stcs(opm + (J) * (long)ROWF, 3.0f * t); \
    } }

#define MIXB(PB) { MIX1(PB,0) MIX1(PB,1) MIX1(PB,2) MIX1(PB,3) \
                   rom += 4; opm += 4 * (long)ROWF; }

#define CPWAIT(N) asm volatile("cp.async.wait_group " #N ";\n" ::: "memory")

// ONE barrier per batch; stage buf (SB+2)&3 was fully read 2 batches ago.
// MIX consumes ds[] of the previous batch BEFORE ROWE refills it.
#define BB(SB, S0, PH, DOMIX, DOISS, WN) { \
    CPWAIT(WN); __syncthreads(); \
    if (DOISS) ISSUE(rb + 8, ((SB)+2)&3) \
    if (DOMIX) { MIXB((PH)^1) } \
    const float* stgf = stage + (SB) * BUFF; \
    ROWE((S0)+0, 0, PH) ROWE((S0)+1, 1, PH) \
    ROWE((S0)+2, 2, PH) ROWE((S0)+3, 3, PH) \
    rb += 4; }

    // prologue: batches 0,1 in flight
    ISSUE(rb,     0)
    ISSUE(rb + 4, 1)

    // warm-up: batches 0..6 (rows h0-22 .. h0+5; batch 6 computes ro h0..h0+3)
    BB(0,0,0, 0,1,1) BB(1,4,1, 0,1,1) BB(2,0,0, 0,1,1) BB(3,4,1, 0,1,1)
    BB(0,0,0, 0,1,1) BB(1,4,1, 0,1,1) BB(2,0,0, 0,1,1)

    // steady state: batches 7..46 (MIX batch k-1)
#pragma unroll 1
    for (int p = 0; p < 10; ++p) {
        BB(3,4,1, 1,1,1) BB(0,0,0, 1,1,1) BB(1,4,1, 1,1,1) BB(2,0,0, 1,1,1)
    }

    // tail: batches 47..50 (last ISSUE at k=48 -> batch 50)
    BB(3,4,1, 1,1,1) BB(0,0,0, 1,1,1) BB(1,4,1, 1,0,1) BB(2,0,0, 1,0,0)

    // epilogue: MIX batch 50 (rows h0+176..h0+179, predicated by hend)
    __syncthreads();
    MIXB(0)

#undef BB
#undef CPWAIT
#undef MIXB
#undef MIX1
#undef ROWE
#undef ISSUE
}

extern "C" void kernel_launch(void* const* d_in, const int* in_sizes, int n_in,
                              void* d_out, int out_size)
{
    const float* D   = (const float*)d_in[0];   // (4096, 4096, 3) f32
    const float* Cm  = (const float*)d_in[1];   // (3, 3) f32
    float*       out = (float*)d_out;           // (4096, 4096, 3) f32
    dim3 grid(64, 23);                          // 1472 blocks ~= 10/SM x 148 SMs
    chem_kernel<<<grid, TPB>>>(D, Cm, out);
}

// round 17
// speedup vs baseline: 1.1219x; 1.1219x over previous
#include <cuda_runtime.h>
typedef unsigned int u32;

#define HH 4096
#define ROWF 12288          // floats per image row
#define TPB 384             // one thread per (col, chan)
#define RS 408              // floats per staged row (128+8 halo cols)
#define BUFF 1632           // floats per 4-row stage buffer
#define BUFB 6528           // bytes per 4-row stage buffer

// horizontal taps: radius-1, renormalized to unit applied mass
#define KH0 0.78698593f
#define KH1 0.10650699f
// vertical taps: radius-2, reference-normalized
#define K0f 0.78657070f
#define K1f 0.10645078f
#define K2f 2.63866e-4f
#define DECAYf 0.60653065971263342f
#define OMDf   0.39346934028736658f
#define INV3f  0.33333322222f        // 1/(3 + 1e-6)

__global__ __launch_bounds__(TPB, 5)
void chem_kernel(const float* __restrict__ D, const float* __restrict__ Cm,
                 float* __restrict__ out)
{
    __shared__ float stage[4 * BUFF];    // 26112 B, 4-deep 4-row ring
    __shared__ float shI[2][4][TPB];     // 12288 B, batch-parity double buffer

    const int tid = threadIdx.x;
    const int c   = tid % 3;
    const int wb_ = tid - c;
    const int w0  = blockIdx.x << 7;     // 32 strips of 128 cols
    const int by  = blockIdx.y;          // 23 row chunks: 179,179,178*21
    const int h0  = 178 * by + (by < 2 ? by : 2);
    const int hend = h0 + (by < 2 ? 179 : 178);

    const float cc0 = __ldg(Cm + 0 + c);
    const float cc1 = __ldg(Cm + 3 + c);
    const float cc2 = __ldg(Cm + 6 + c);

    // cp.async loader: vec v of 408 -> (row v/102, lane v%102)
    const int  j0   = tid / 102, v0 = tid - 102 * j0;
    const int  g0   = (w0 - 4) * 3 + 4 * v0;           // row-relative float idx
    const bool cok0 = (g0 >= 0) && (g0 + 4 <= ROWF);
    const bool sec  = tid < 24;                        // vecs 384..407 (row 3)
    const int  g1   = (w0 - 4) * 3 + 4 * (78 + tid);
    const bool cok1 = sec && (g1 >= 0) && (g1 + 4 <= ROWF);

    const u32 sb  = (u32)__cvta_generic_to_shared(stage);
    const u32 sA0 = sb + (u32)((j0 * RS + 4 * v0) * 4);
    const u32 sA1 = sb + (u32)((3 * RS + 4 * (78 + tid)) * 4);

    float hb[8] = {0,0,0,0,0,0,0,0};   // horizontal-blur ring
    float dr[4] = {0,0,0,0};           // raw density ring (lag 2)
    float sr[4] = {0,0,0,0};           // soft-cloud ring (lag 2)
    float ds[4];                       // density stash (MIX consumes pre-refill)
    float siir = 0.f;

    int rb  = h0 - 26;                 // 52 batches of 4 rows; MIX from k=8
    int rom = h0;                      // MIX row base
    float* opm = out + (long)h0 * ROWF + w0 * 3 + tid;

#define ISSUE(RB, SBUF) { \
    const int  row = (RB) + j0; \
    const int  sz  = (cok0 && row >= 0 && row < HH) ? 16 : 0; \
    const float* gp = sz ? (D + (long)row * ROWF + g0) : D; \
    asm volatile("cp.async.cg.shared.global [%0], [%1], 16, %2;\n" \
                 :: "r"(sA0 + (u32)(SBUF) * BUFB), "l"(gp), "r"(sz) : "memory"); \
    if (sec) { \
        const int  row1 = (RB) + 3; \
        const int  sz1  = (cok1 && row1 >= 0 && row1 < HH) ? 16 : 0; \
        const float* gp1 = sz1 ? (D + (long)row1 * ROWF + g1) : D; \
        asm volatile("cp.async.cg.shared.global [%0], [%1], 16, %2;\n" \
                     :: "r"(sA1 + (u32)(SBUF) * BUFB), "l"(gp1), "r"(sz1) : "memory"); \
    } \
    asm volatile("cp.async.commit_group;\n" ::: "memory"); }

// Row at phase S; output row ro = r-2 (lag-2 rings). shI/ds always written;
// warm batches' values are simply never MIXed.
#define ROWE(S, J, PH) { \
    const float* bp = stgf + (J) * RS; \
    const float xm1 = bp[tid+9], x0 = bp[tid+12], xp1 = bp[tid+15]; \
    siir = fmaf(DECAYf, siir, x0); \
    hb[(S)&7] = fmaf(xm1 + xp1, KH1, x0 * KH0); \
    float vb_ = hb[((S)+6)&7] * K0f; \
    vb_ = fmaf(hb[((S)+5)&7] + hb[((S)+7)&7], K1f, vb_); \
    vb_ = fmaf(hb[((S)+4)&7] + hb[(S)&7],     K2f, vb_); \
    const float d_o = dr[((S)+2)&3]; \
    const float s_o = sr[((S)+2)&3]; \
    ds[J] = d_o; \
    shI[PH][J][tid] = s_o + (d_o * INV3f) * (vb_ - s_o); \
    dr[(S)&3] = x0; \
    sr[(S)&3] = OMDf * siir; }

#define MIX1(PB, J) { \
    if (rom + (J) < hend) { \
        const float i0 = shI[PB][J][wb_], i1 = shI[PB][J][wb_+1], i2 = shI[PB][J][wb_+2]; \
        const float inh = cc0*i0 + cc1*i1 + cc2*i2; \
        const float arg = (ds[J] - inh) * INV3f; \
        float t; asm("tanh.approx.f32 %0, %1;" : "=f"(t) : "f"(arg)); \
        __stcs(opm + (J) * (long)ROWF, 3.0f * t); \
    } }

#define MIXB(PB) { MIX1(PB,0) MIX1(PB,1) MIX1(PB,2) MIX1(PB,3) \
                   rom += 4; opm += 4 * (long)ROWF; }

#define CPWAIT(N) asm volatile("cp.async.wait_group " #N ";\n" ::: "memory")

// ONE barrier per batch; depth-3 issue-ahead uses all 4 ring buffers.
// At batch k: wait_group 2 -> group k landed; ISSUE k+3 into buf (k-1)&3,
// whose reads completed before barrier k. MIX consumes ds[] before refill.
#define BB(SB, S0, PH, DOMIX, DOISS, WN) { \
    CPWAIT(WN); __syncthreads(); \
    if (DOISS) ISSUE(rb + 12, ((SB)+3)&3) \
    if (DOMIX) { MIXB((PH)^1) } \
    const float* stgf = stage + (SB) * BUFF; \
    ROWE((S0)+0, 0, PH) ROWE((S0)+1, 1, PH) \
    ROWE((S0)+2, 2, PH) ROWE((S0)+3, 3, PH) \
    rb += 4; }

    // prologue: batches 0,1,2 in flight (12-row slack)
    ISSUE(rb,     0)
    ISSUE(rb + 4, 1)
    ISSUE(rb + 8, 2)

    // warm-up: batches 0..7 (commit rows h0-26 .. h0+5; MIX not started)
    BB(0,0,0, 0,1,2) BB(1,4,1, 0,1,2) BB(2,0,0, 0,1,2) BB(3,4,1, 0,1,2)
    BB(0,0,0, 0,1,2) BB(1,4,1, 0,1,2) BB(2,0,0, 0,1,2) BB(3,4,1, 0,1,2)

    // steady state: batches 8..47 (MIX batch k-1)
#pragma unroll 1
    for (int p = 0; p < 10; ++p) {
        BB(0,0,0, 1,1,2) BB(1,4,1, 1,1,2) BB(2,0,0, 1,1,2) BB(3,4,1, 1,1,2)
    }

    // tail: batches 48..51 (last ISSUE at k=48 -> batch 51)
    BB(0,0,0, 1,1,2) BB(1,4,1, 1,0,2) BB(2,0,0, 1,0,1) BB(3,4,1, 1,0,0)

    // epilogue: MIX batch 51 (rows h0+176..h0+179, predicated by hend)
    __syncthreads();
    MIXB(1)

#undef BB
#undef CPWAIT
#undef MIXB
#undef MIX1
#undef ROWE
#undef ISSUE
}

extern "C" void kernel_launch(void* const* d_in, const int* in_sizes, int n_in,
                              void* d_out, int out_size)
{
    const float* D   = (const float*)d_in[0];   // (4096, 4096, 3) f32
    const float* Cm  = (const float*)d_in[1];   // (3, 3) f32
    float*       out = (float*)d_out;           // (4096, 4096, 3) f32
    dim3 grid(32, 23);                          // 736 blocks ~= 5/SM x 148 SMs
    chem_kernel<<<grid, TPB>>>(D, Cm, out);
}